// round 6
// baseline (speedup 1.0000x reference)
#include <cuda_runtime.h>

// Batched Kalman filter: B=262144, N=8, M=4, fp32.
// 4 threads per batch (thread s owns rows {s, s+4}). All intra-quad data
// exchange via register shuffles (width-4); smem only for coalesced gmem
// staging and own-row loads. Outputs flat: x_new[B,8], P_new[B,8,8], K[B,8,4].

constexpr int BT  = 262144;
constexpr int TPB = 128;
constexpr int G   = 32;
constexpr float EPS = 1e-6f;

constexpr int SF = 68;
constexpr int SH = 36;
constexpr int SR = 20;
constexpr int SX = 12;
constexpr int SZ = 12;

template<int E, int S>
__device__ __forceinline__ void stage_in(float* sm, const float* __restrict__ gp,
                                         int b0, int tid) {
    const float4* g4 = reinterpret_cast<const float4*>(gp + (size_t)b0 * E);
    constexpr int T4 = G * E / 4;
#pragma unroll
    for (int i = tid; i < T4; i += TPB) {
        float4 v = g4[i];
        int e = i * 4;
        *reinterpret_cast<float4*>(sm + (e / E) * S + (e % E)) = v;
    }
}

template<int E, int S>
__device__ __forceinline__ void stage_out(float* __restrict__ gp, const float* sm,
                                          int b0, int tid) {
    float4* g4 = reinterpret_cast<float4*>(gp + (size_t)b0 * E);
    constexpr int T4 = G * E / 4;
#pragma unroll
    for (int i = tid; i < T4; i += TPB) {
        int e = i * 4;
        g4[i] = *reinterpret_cast<const float4*>(sm + (e / E) * S + (e % E));
    }
}

__device__ __forceinline__ void ld_row8(float* d, const float* s) {
    float4 a = *reinterpret_cast<const float4*>(s);
    float4 b = *reinterpret_cast<const float4*>(s + 4);
    d[0]=a.x; d[1]=a.y; d[2]=a.z; d[3]=a.w;
    d[4]=b.x; d[5]=b.y; d[6]=b.z; d[7]=b.w;
}
__device__ __forceinline__ void st_row8(float* d, const float* s) {
    *reinterpret_cast<float4*>(d)     = make_float4(s[0], s[1], s[2], s[3]);
    *reinterpret_cast<float4*>(d + 4) = make_float4(s[4], s[5], s[6], s[7]);
}

// broadcast from lane `src` within the 4-lane quad
__device__ __forceinline__ float qshfl(float v, int src) {
    return __shfl_sync(0xffffffffu, v, src, 4);
}

__global__ __launch_bounds__(TPB, 5) void kf_kernel(
    const float* __restrict__ gx, const float* __restrict__ gP,
    const float* __restrict__ gF, const float* __restrict__ gQ,
    const float* __restrict__ gz, const float* __restrict__ gH,
    const float* __restrict__ gR, float* __restrict__ out)
{
    __shared__ __align__(16) float sm[9088];   // 36.4 KB
    float* sF = sm;                // G*68
    float* sP = sm + 2176;
    float* sQ = sm + 4352;
    float* sH = sm + 6528;         // K output after H dead
    float* sR = sm + 7680;
    float* sx = sm + 8320;
    float* sz = sm + 8704;

    const int tid = threadIdx.x;
    const int b0  = blockIdx.x * G;
    const int g   = tid >> 2;
    const int s   = tid & 3;
    const int r0  = s, r1 = s + 4;

    stage_in<64, SF>(sF, gF, b0, tid);
    stage_in<8, SX>(sx, gx, b0, tid);
    stage_in<64, SF>(sP, gP, b0, tid);
    stage_in<64, SF>(sQ, gQ, b0, tid);
    stage_in<32, SH>(sH, gH, b0, tid);
    stage_in<16, SR>(sR, gR, b0, tid);
    stage_in<4, SZ>(sz, gz, b0, tid);
    __syncthreads();

    float* Fb = sF + g * SF;
    float* Pb = sP + g * SF;
    float* Qb = sQ + g * SF;
    float* Hb = sH + g * SH;
    float* Rb = sR + g * SR;
    float* xb = sx + g * SX;
    float* zb = sz + g * SZ;

    // ---- own F rows; x_pred ----
    float f0[8], f1[8];
    ld_row8(f0, Fb + r0 * 8);
    ld_row8(f1, Fb + r1 * 8);
    float xv[8];
    ld_row8(xv, xb);
    float xp0 = 0.f, xp1 = 0.f;
#pragma unroll
    for (int j = 0; j < 8; ++j) { xp0 += f0[j]*xv[j]; xp1 += f1[j]*xv[j]; }

    // ---- own P rows; T rows via quad shuffle of P ----
    float p0[8], p1[8];
    ld_row8(p0, Pb + r0 * 8);
    ld_row8(p1, Pb + r1 * 8);
    float t0[8], t1[8];
#pragma unroll
    for (int j = 0; j < 8; ++j) { t0[j] = 0.f; t1[j] = 0.f; }
#pragma unroll
    for (int k = 0; k < 8; ++k) {
        float fk0 = f0[k], fk1 = f1[k];
#pragma unroll
        for (int j = 0; j < 8; ++j) {
            float pkj = qshfl(k < 4 ? p0[j] : p1[j], k & 3);
            t0[j] += fk0 * pkj; t1[j] += fk1 * pkj;
        }
    }

    // ---- P_pred rows: F rows via quad shuffle ----
    float pp0[8], pp1[8];
    {
        float q0[8], q1[8];
        ld_row8(q0, Qb + r0 * 8);
        ld_row8(q1, Qb + r1 * 8);
#pragma unroll
        for (int j = 0; j < 8; ++j) {
            float u0 = q0[j], u1 = q1[j];
#pragma unroll
            for (int k = 0; k < 8; ++k) {
                float fjk = qshfl(j < 4 ? f0[k] : f1[k], j & 3);
                u0 += t0[k]*fjk; u1 += t1[k]*fjk;
            }
            pp0[j] = u0; pp1[j] = u1;
        }
    }

    // ---- A rows: A[r][m] = pp[r] . H[m] (H rows from smem) ----
    float a0[4], a1[4];
#pragma unroll
    for (int m = 0; m < 4; ++m) {
        float hr[8];
        ld_row8(hr, Hb + m * 8);
        float u0 = 0.f, u1 = 0.f;
#pragma unroll
        for (int j = 0; j < 8; ++j) { u0 += pp0[j]*hr[j]; u1 += pp1[j]*hr[j]; }
        a0[m] = u0; a1[m] = u1;
    }

    // ---- S row s: R[s] + eps*e_s + sum_i H[s][i] * A[i][:]  (A via shuffle) ----
    float hs[8];
    ld_row8(hs, Hb + s * 8);
    float ac0, ac1, ac2, ac3;
    {
        float4 rr = *reinterpret_cast<const float4*>(Rb + s * 4);
        ac0 = rr.x + (s == 0 ? EPS : 0.f);
        ac1 = rr.y + (s == 1 ? EPS : 0.f);
        ac2 = rr.z + (s == 2 ? EPS : 0.f);
        ac3 = rr.w + (s == 3 ? EPS : 0.f);
#pragma unroll
        for (int i = 0; i < 8; ++i) {
            float hi = hs[i];
            ac0 += hi * qshfl(i < 4 ? a0[0] : a1[0], i & 3);
            ac1 += hi * qshfl(i < 4 ? a0[1] : a1[1], i & 3);
            ac2 += hi * qshfl(i < 4 ? a0[2] : a1[2], i & 3);
            ac3 += hi * qshfl(i < 4 ? a0[3] : a1[3], i & 3);
        }
    }

    // ---- y[s] distributed, then broadcast via shuffle ----
    float yown;
    {
        float acc = zb[s];
#pragma unroll
        for (int i = 0; i < 8; ++i) {
            float xpi = qshfl(i < 4 ? xp0 : xp1, i & 3);
            acc -= hs[i] * xpi;
        }
        yown = acc;
    }
    float y[4];
#pragma unroll
    for (int m = 0; m < 4; ++m) y[m] = qshfl(yown, m);

    // ---- gather S lower triangle via shuffle; Cholesky (per thread) ----
    float s00 = qshfl(ac0, 0);
    float s10 = qshfl(ac0, 1), s11 = qshfl(ac1, 1);
    float s20 = qshfl(ac0, 2), s21 = qshfl(ac1, 2), s22 = qshfl(ac2, 2);
    float s30 = qshfl(ac0, 3), s31 = qshfl(ac1, 3), s32 = qshfl(ac2, 3), s33 = qshfl(ac3, 3);

    float iL00 = rsqrtf(s00);
    float L10 = s10 * iL00, L20 = s20 * iL00, L30 = s30 * iL00;
    float iL11 = rsqrtf(s11 - L10*L10);
    float L21 = (s21 - L20*L10) * iL11;
    float L31 = (s31 - L30*L10) * iL11;
    float iL22 = rsqrtf(s22 - L20*L20 - L21*L21);
    float L32 = (s32 - L30*L20 - L31*L21) * iL22;
    float iL33 = rsqrtf(s33 - L30*L30 - L31*L31 - L32*L32);

    // ---- K rows (own): solve S k = a ----
    float k0[4], k1[4];
    {
        float w0 = a0[0] * iL00;
        float w1 = (a0[1] - L10*w0) * iL11;
        float w2 = (a0[2] - L20*w0 - L21*w1) * iL22;
        float w3 = (a0[3] - L30*w0 - L31*w1 - L32*w2) * iL33;
        k0[3] = w3 * iL33;
        k0[2] = (w2 - L32*k0[3]) * iL22;
        k0[1] = (w1 - L21*k0[2] - L31*k0[3]) * iL11;
        k0[0] = (w0 - L10*k0[1] - L20*k0[2] - L30*k0[3]) * iL00;
    }
    {
        float w0 = a1[0] * iL00;
        float w1 = (a1[1] - L10*w0) * iL11;
        float w2 = (a1[2] - L20*w0 - L21*w1) * iL22;
        float w3 = (a1[3] - L30*w0 - L31*w1 - L32*w2) * iL33;
        k1[3] = w3 * iL33;
        k1[2] = (w2 - L32*k1[3]) * iL22;
        k1[1] = (w1 - L21*k1[2] - L31*k1[3]) * iL11;
        k1[0] = (w0 - L10*k1[1] - L20*k1[2] - L30*k1[3]) * iL00;
    }

    // ---- x_new own rows ----
    float xn0 = xp0, xn1 = xp1;
#pragma unroll
    for (int m = 0; m < 4; ++m) { xn0 += k0[m]*y[m]; xn1 += k1[m]*y[m]; }

    // ---- P_new rows: pn[r][j] = pp[r][j] - K[r] . A[j]  (HP = A^T, A via shuffle) ----
    float pn0[8], pn1[8];
#pragma unroll
    for (int j = 0; j < 8; ++j) {
        float aj0 = qshfl(j < 4 ? a0[0] : a1[0], j & 3);
        float aj1 = qshfl(j < 4 ? a0[1] : a1[1], j & 3);
        float aj2 = qshfl(j < 4 ? a0[2] : a1[2], j & 3);
        float aj3 = qshfl(j < 4 ? a0[3] : a1[3], j & 3);
        pn0[j] = pp0[j] - (k0[0]*aj0 + k0[1]*aj1 + k0[2]*aj2 + k0[3]*aj3);
        pn1[j] = pp1[j] - (k1[0]*aj0 + k1[1]*aj1 + k1[2]*aj2 + k1[3]*aj3);
    }

    // ---- stores: quad lanes still read Hb/xb above -> one syncwarp guard ----
    __syncwarp();
    st_row8(Fb + r0 * 8, pn0);
    st_row8(Fb + r1 * 8, pn1);
    xb[r0] = xn0; xb[r1] = xn1;
    *reinterpret_cast<float4*>(Hb + r0 * 4) = make_float4(k0[0], k0[1], k0[2], k0[3]);
    *reinterpret_cast<float4*>(Hb + r1 * 4) = make_float4(k1[0], k1[1], k1[2], k1[3]);

    __syncthreads();
    stage_out<8, SX>(out, sx, b0, tid);
    stage_out<64, SF>(out + (size_t)8 * BT, sF, b0, tid);
    stage_out<32, SH>(out + (size_t)72 * BT, sH, b0, tid);
}

extern "C" void kernel_launch(void* const* d_in, const int* in_sizes, int n_in,
                              void* d_out, int out_size) {
    const float* x_est = (const float*)d_in[0];
    const float* P_est = (const float*)d_in[1];
    const float* F     = (const float*)d_in[2];
    const float* Q     = (const float*)d_in[3];
    const float* z     = (const float*)d_in[4];
    const float* H     = (const float*)d_in[5];
    const float* R     = (const float*)d_in[6];
    float* out = (float*)d_out;

    kf_kernel<<<BT / G, TPB>>>(x_est, P_est, F, Q, z, H, R, out);
}